// round 1
// baseline (speedup 1.0000x reference)
#include <cuda_runtime.h>

#define NC 22
#define NP 1024
#define TPB 256
#define CHUNKS 4           // NP / CHUNKS must equal TPB
#define MARGIN 0.01f

__device__ __forceinline__ void quat2rot(float w, float x, float y, float z, float* R) {
    R[0] = 1.f - 2.f * (y * y + z * z);
    R[1] = 2.f * (x * y - z * w);
    R[2] = 2.f * (x * z + y * w);
    R[3] = 2.f * (x * y + z * w);
    R[4] = 1.f - 2.f * (x * x + z * z);
    R[5] = 2.f * (y * z - x * w);
    R[6] = 2.f * (x * z - y * w);
    R[7] = 2.f * (y * z + x * w);
    R[8] = 1.f - 2.f * (x * x + y * y);
}

__global__ void adl_zero_kernel(float* out, int n) {
    int i = blockIdx.x * blockDim.x + threadIdx.x;
    if (i < n) out[i] = 0.f;
}

__global__ __launch_bounds__(TPB) void AverageDistanceLoss_kernel(
    const float* __restrict__ poses_pred,
    const float* __restrict__ poses_target,
    const float* __restrict__ poses_weight,
    const float* __restrict__ points,
    const float* __restrict__ symmetry,
    float* __restrict__ out,
    float inv_scale)
{
    __shared__ float4 s_xg[NP];        // (-2*xg.x, -2*xg.y, -2*xg.z, ||xg||^2)
    __shared__ float  s_red[TPB / 32];

    const int b     = blockIdx.x;
    const int chunk = blockIdx.y;
    const int tid   = threadIdx.x;

    // ---- class selection: first i with weight[b, 4i] > 0 ----
    int  cls   = 0;
    bool valid = false;
    #pragma unroll
    for (int i = 0; i < NC; i++) {
        float w = poses_weight[b * 4 * NC + 4 * i];
        if (!valid && w > 0.f) { cls = i; valid = true; }
    }

    const float* qp = poses_pred   + b * 4 * NC + 4 * cls;
    const float* qg = poses_target + b * 4 * NC + 4 * cls;
    float Rp[9], Rg[9];
    quat2rot(qp[0], qp[1], qp[2], qp[3], Rp);
    quat2rot(qg[0], qg[1], qg[2], qg[3], Rg);

    const bool   sym = symmetry[cls] > 0.f;
    const float* pts = points + (size_t)cls * NP * 3;

    // ---- build target-pose point cache in shared ----
    for (int i = tid; i < NP; i += TPB) {
        float px = pts[i * 3 + 0];
        float py = pts[i * 3 + 1];
        float pz = pts[i * 3 + 2];
        float gx = Rg[0] * px + Rg[1] * py + Rg[2] * pz;
        float gy = Rg[3] * px + Rg[4] * py + Rg[5] * pz;
        float gz = Rg[6] * px + Rg[7] * py + Rg[8] * pz;
        float nq = gx * gx + gy * gy + gz * gz;
        s_xg[i] = make_float4(-2.f * gx, -2.f * gy, -2.f * gz, nq);
    }
    __syncthreads();

    // ---- my point p (one per thread within this chunk) ----
    const int p = chunk * (NP / CHUNKS) + tid;
    float px = pts[p * 3 + 0];
    float py = pts[p * 3 + 1];
    float pz = pts[p * 3 + 2];
    float ax = Rp[0] * px + Rp[1] * py + Rp[2] * pz;
    float ay = Rp[3] * px + Rp[4] * py + Rp[5] * pz;
    float az = Rp[6] * px + Rp[7] * py + Rp[8] * pz;
    float np2 = ax * ax + ay * ay + az * az;

    float d;
    if (sym) {
        // min over q of (||xg_q||^2 - 2*xp.xg_q); add ||xp||^2 (constant) after the min
        float mn = 3.4e38f;
        #pragma unroll 8
        for (int q = 0; q < NP; q++) {
            float4 g = s_xg[q];   // broadcast LDS.128
            float dd = fmaf(ax, g.x, fmaf(ay, g.y, fmaf(az, g.z, g.w)));
            mn = fminf(mn, dd);
        }
        d = fmaxf(mn + np2, 0.f);   // clamp commutes with min
    } else {
        float4 g = s_xg[p];         // xg = -0.5 * g.xyz
        float dx = fmaf(0.5f, g.x, ax);
        float dy = fmaf(0.5f, g.y, ay);
        float dz = fmaf(0.5f, g.z, az);
        d = dx * dx + dy * dy + dz * dz;
    }

    float contrib = valid ? 0.5f * fmaxf(d - MARGIN, 0.f) * inv_scale : 0.f;

    // ---- block reduction ----
    #pragma unroll
    for (int off = 16; off > 0; off >>= 1)
        contrib += __shfl_down_sync(0xFFFFFFFFu, contrib, off);
    if ((tid & 31) == 0) s_red[tid >> 5] = contrib;
    __syncthreads();
    if (tid < 32) {
        float v = (tid < TPB / 32) ? s_red[tid] : 0.f;
        #pragma unroll
        for (int off = 4; off > 0; off >>= 1)
            v += __shfl_down_sync(0xFFFFFFFFu, v, off);
        if (tid == 0) atomicAdd(out, v);
    }
}

extern "C" void kernel_launch(void* const* d_in, const int* in_sizes, int n_in,
                              void* d_out, int out_size) {
    const float* poses_pred   = (const float*)d_in[0];
    const float* poses_target = (const float*)d_in[1];
    const float* poses_weight = (const float*)d_in[2];
    const float* points       = (const float*)d_in[3];
    const float* symmetry     = (const float*)d_in[4];
    float* out = (float*)d_out;

    const int B = in_sizes[0] / (4 * NC);
    const float inv_scale = 1.0f / ((float)B * (float)NP);

    adl_zero_kernel<<<(out_size + 255) / 256, 256>>>(out, out_size);

    dim3 grid(B, CHUNKS);
    AverageDistanceLoss_kernel<<<grid, TPB>>>(
        poses_pred, poses_target, poses_weight, points, symmetry, out, inv_scale);
}

// round 2
// speedup vs baseline: 1.0230x; 1.0230x over previous
#include <cuda_runtime.h>

#define NC 22
#define NP 1024
#define TPB 256
#define CHUNKS 4           // NP / CHUNKS must equal TPB
#define MARGIN 0.01f

typedef unsigned long long ull;

__device__ __forceinline__ ull fma2(ull a, ull b, ull c) {
    ull d;
    asm("fma.rn.f32x2 %0, %1, %2, %3;" : "=l"(d) : "l"(a), "l"(b), "l"(c));
    return d;
}
__device__ __forceinline__ ull pack2(float lo, float hi) {
    ull d;
    asm("mov.b64 %0, {%1, %2};" : "=l"(d) : "f"(lo), "f"(hi));
    return d;
}
__device__ __forceinline__ void unpack2(ull v, float& lo, float& hi) {
    asm("mov.b64 {%0, %1}, %2;" : "=f"(lo), "=f"(hi) : "l"(v));
}

__device__ __forceinline__ void quat2rot(float w, float x, float y, float z, float* R) {
    R[0] = 1.f - 2.f * (y * y + z * z);
    R[1] = 2.f * (x * y - z * w);
    R[2] = 2.f * (x * z + y * w);
    R[3] = 2.f * (x * y + z * w);
    R[4] = 1.f - 2.f * (x * x + z * z);
    R[5] = 2.f * (y * z - x * w);
    R[6] = 2.f * (x * z - y * w);
    R[7] = 2.f * (y * z + x * w);
    R[8] = 1.f - 2.f * (x * x + y * y);
}

__global__ void adl_zero_kernel(float* out, int n) {
    int i = blockIdx.x * blockDim.x + threadIdx.x;
    if (i < n) out[i] = 0.f;
}

__global__ __launch_bounds__(TPB) void AverageDistanceLoss_kernel(
    const float* __restrict__ poses_pred,
    const float* __restrict__ poses_target,
    const float* __restrict__ poses_weight,
    const float* __restrict__ points,
    const float* __restrict__ symmetry,
    float* __restrict__ out,
    float inv_scale)
{
    // Pair-packed SoA of target-pose points:
    //   s_A[j] = ( (-2gx_e,-2gx_o) , (-2gy_e,-2gy_o) )  as two b64
    //   s_B[j] = ( (-2gz_e,-2gz_o) , (|g_e|^2,|g_o|^2) )
    __shared__ ulonglong2 s_A[NP / 2];
    __shared__ ulonglong2 s_B[NP / 2];
    __shared__ float s_red[TPB / 32];

    const int b     = blockIdx.x;
    const int chunk = blockIdx.y;
    const int tid   = threadIdx.x;

    // ---- class selection: first i with weight[b, 4i] > 0 ----
    int  cls   = 0;
    bool valid = false;
    #pragma unroll
    for (int i = 0; i < NC; i++) {
        float w = poses_weight[b * 4 * NC + 4 * i];
        if (!valid && w > 0.f) { cls = i; valid = true; }
    }

    const float* qp = poses_pred   + b * 4 * NC + 4 * cls;
    const float* qg = poses_target + b * 4 * NC + 4 * cls;
    float Rp[9], Rg[9];
    quat2rot(qp[0], qp[1], qp[2], qp[3], Rp);
    quat2rot(qg[0], qg[1], qg[2], qg[3], Rg);

    const bool   sym = symmetry[cls] > 0.f;
    const float* pts = points + (size_t)cls * NP * 3;

    // ---- build packed target-pose cache in shared ----
    for (int j = tid; j < NP / 2; j += TPB) {
        const float* p0 = pts + (size_t)(2 * j) * 3;
        float x0 = p0[0], y0 = p0[1], z0 = p0[2];
        float x1 = p0[3], y1 = p0[4], z1 = p0[5];

        float gx0 = Rg[0] * x0 + Rg[1] * y0 + Rg[2] * z0;
        float gy0 = Rg[3] * x0 + Rg[4] * y0 + Rg[5] * z0;
        float gz0 = Rg[6] * x0 + Rg[7] * y0 + Rg[8] * z0;
        float gx1 = Rg[0] * x1 + Rg[1] * y1 + Rg[2] * z1;
        float gy1 = Rg[3] * x1 + Rg[4] * y1 + Rg[5] * z1;
        float gz1 = Rg[6] * x1 + Rg[7] * y1 + Rg[8] * z1;
        float n0 = gx0 * gx0 + gy0 * gy0 + gz0 * gz0;
        float n1 = gx1 * gx1 + gy1 * gy1 + gz1 * gz1;

        ulonglong2 A, B;
        A.x = pack2(-2.f * gx0, -2.f * gx1);
        A.y = pack2(-2.f * gy0, -2.f * gy1);
        B.x = pack2(-2.f * gz0, -2.f * gz1);
        B.y = pack2(n0, n1);
        s_A[j] = A;
        s_B[j] = B;
    }
    __syncthreads();

    // ---- my point p, rotated by predicted pose ----
    const int p = chunk * (NP / CHUNKS) + tid;
    float px = pts[p * 3 + 0];
    float py = pts[p * 3 + 1];
    float pz = pts[p * 3 + 2];
    float ax = Rp[0] * px + Rp[1] * py + Rp[2] * pz;
    float ay = Rp[3] * px + Rp[4] * py + Rp[5] * pz;
    float az = Rp[6] * px + Rp[7] * py + Rp[8] * pz;
    float np2 = ax * ax + ay * ay + az * az;

    float d;
    if (sym) {
        const ull ax2 = pack2(ax, ax);
        const ull ay2 = pack2(ay, ay);
        const ull az2 = pack2(az, az);
        float mn0 = 3.4e38f, mn1 = 3.4e38f;
        #pragma unroll 4
        for (int j = 0; j < NP / 2; j++) {
            ulonglong2 A = s_A[j];   // broadcast LDS.128
            ulonglong2 B = s_B[j];   // broadcast LDS.128
            ull dd = fma2(az2, B.x, B.y);      // -2*az*gz + |g|^2   (x2)
            dd = fma2(ay2, A.y, dd);
            dd = fma2(ax2, A.x, dd);
            float lo, hi;
            unpack2(dd, lo, hi);
            mn0 = fminf(mn0, lo);
            mn1 = fminf(mn1, hi);
        }
        // max(.,0) commutes with min; add constant |xp|^2 after the min
        d = fmaxf(fminf(mn0, mn1) + np2, 0.f);
    } else {
        float gx = Rg[0] * px + Rg[1] * py + Rg[2] * pz;
        float gy = Rg[3] * px + Rg[4] * py + Rg[5] * pz;
        float gz = Rg[6] * px + Rg[7] * py + Rg[8] * pz;
        float dx = ax - gx, dy = ay - gy, dz = az - gz;
        d = dx * dx + dy * dy + dz * dz;
    }

    float contrib = valid ? 0.5f * fmaxf(d - MARGIN, 0.f) * inv_scale : 0.f;

    // ---- block reduction ----
    #pragma unroll
    for (int off = 16; off > 0; off >>= 1)
        contrib += __shfl_down_sync(0xFFFFFFFFu, contrib, off);
    if ((tid & 31) == 0) s_red[tid >> 5] = contrib;
    __syncthreads();
    if (tid < 32) {
        float v = (tid < TPB / 32) ? s_red[tid] : 0.f;
        #pragma unroll
        for (int off = 4; off > 0; off >>= 1)
            v += __shfl_down_sync(0xFFFFFFFFu, v, off);
        if (tid == 0) atomicAdd(out, v);
    }
}

extern "C" void kernel_launch(void* const* d_in, const int* in_sizes, int n_in,
                              void* d_out, int out_size) {
    const float* poses_pred   = (const float*)d_in[0];
    const float* poses_target = (const float*)d_in[1];
    const float* poses_weight = (const float*)d_in[2];
    const float* points       = (const float*)d_in[3];
    const float* symmetry     = (const float*)d_in[4];
    float* out = (float*)d_out;

    const int B = in_sizes[0] / (4 * NC);
    const float inv_scale = 1.0f / ((float)B * (float)NP);

    adl_zero_kernel<<<(out_size + 255) / 256, 256>>>(out, out_size);

    dim3 grid(B, CHUNKS);
    AverageDistanceLoss_kernel<<<grid, TPB>>>(
        poses_pred, poses_target, poses_weight, points, symmetry, out, inv_scale);
}

// round 4
// speedup vs baseline: 1.2295x; 1.2018x over previous
#include <cuda_runtime.h>

#define NC 22
#define NP 1024
#define TPB 128
#define CHUNKS 8           // TPB * CHUNKS == NP
#define MARGIN 0.01f

typedef unsigned long long ull;

__device__ __forceinline__ ull fma2(ull a, ull b, ull c) {
    ull d;
    asm("fma.rn.f32x2 %0, %1, %2, %3;" : "=l"(d) : "l"(a), "l"(b), "l"(c));
    return d;
}
__device__ __forceinline__ ull pack2(float lo, float hi) {
    ull d;
    asm("mov.b64 %0, {%1, %2};" : "=l"(d) : "f"(lo), "f"(hi));
    return d;
}
__device__ __forceinline__ void unpack2(ull v, float& lo, float& hi) {
    asm("mov.b64 {%0, %1}, %2;" : "=f"(lo), "=f"(hi) : "l"(v));
}

__device__ __forceinline__ void quat2rot(float w, float x, float y, float z, float* R) {
    R[0] = 1.f - 2.f * (y * y + z * z);
    R[1] = 2.f * (x * y - z * w);
    R[2] = 2.f * (x * z + y * w);
    R[3] = 2.f * (x * y + z * w);
    R[4] = 1.f - 2.f * (x * x + z * z);
    R[5] = 2.f * (y * z - x * w);
    R[6] = 2.f * (x * z - y * w);
    R[7] = 2.f * (y * z + x * w);
    R[8] = 1.f - 2.f * (x * x + y * y);
}

__global__ void adl_zero_kernel(float* out, int n) {
    int i = blockIdx.x * blockDim.x + threadIdx.x;
    if (i < n) out[i] = 0.f;
}

__global__ __launch_bounds__(TPB) void AverageDistanceLoss_kernel(
    const float* __restrict__ poses_pred,
    const float* __restrict__ poses_target,
    const float* __restrict__ poses_weight,
    const float* __restrict__ points,
    const float* __restrict__ symmetry,
    float* __restrict__ out,
    float inv_scale)
{
    // Pair-packed SoA of target-pose points:
    //   s_A[j] = ( (-2gx_e,-2gx_o) , (-2gy_e,-2gy_o) )
    //   s_B[j] = ( (-2gz_e,-2gz_o) , (|g_e|^2,|g_o|^2) )
    __shared__ ulonglong2 s_A[NP / 2];
    __shared__ ulonglong2 s_B[NP / 2];
    __shared__ float s_red[TPB / 32];

    const int b     = blockIdx.x;
    const int chunk = blockIdx.y;
    const int tid   = threadIdx.x;

    // ---- class selection: first i with weight[b, 4i] > 0 ----
    int  cls   = 0;
    bool valid = false;
    #pragma unroll
    for (int i = 0; i < NC; i++) {
        float w = poses_weight[b * 4 * NC + 4 * i];
        if (!valid && w > 0.f) { cls = i; valid = true; }
    }

    const float* qp = poses_pred   + b * 4 * NC + 4 * cls;
    const float* qg = poses_target + b * 4 * NC + 4 * cls;
    float Rp[9], Rg[9];
    quat2rot(qp[0], qp[1], qp[2], qp[3], Rp);
    quat2rot(qg[0], qg[1], qg[2], qg[3], Rg);

    const bool   sym = symmetry[cls] > 0.f;
    const float* pts = points + (size_t)cls * NP * 3;

    // ---- build packed target-pose cache in shared ----
    #pragma unroll
    for (int j = tid; j < NP / 2; j += TPB) {
        const float* p0 = pts + (size_t)(2 * j) * 3;
        float x0 = p0[0], y0 = p0[1], z0 = p0[2];
        float x1 = p0[3], y1 = p0[4], z1 = p0[5];

        float gx0 = Rg[0] * x0 + Rg[1] * y0 + Rg[2] * z0;
        float gy0 = Rg[3] * x0 + Rg[4] * y0 + Rg[5] * z0;
        float gz0 = Rg[6] * x0 + Rg[7] * y0 + Rg[8] * z0;
        float gx1 = Rg[0] * x1 + Rg[1] * y1 + Rg[2] * z1;
        float gy1 = Rg[3] * x1 + Rg[4] * y1 + Rg[5] * z1;
        float gz1 = Rg[6] * x1 + Rg[7] * y1 + Rg[8] * z1;
        float n0 = gx0 * gx0 + gy0 * gy0 + gz0 * gz0;
        float n1 = gx1 * gx1 + gy1 * gy1 + gz1 * gz1;

        ulonglong2 A, B;
        A.x = pack2(-2.f * gx0, -2.f * gx1);
        A.y = pack2(-2.f * gy0, -2.f * gy1);
        B.x = pack2(-2.f * gz0, -2.f * gz1);
        B.y = pack2(n0, n1);
        s_A[j] = A;
        s_B[j] = B;
    }
    __syncthreads();

    // ---- my point p, rotated by predicted pose ----
    const int p = chunk * TPB + tid;
    float px = pts[p * 3 + 0];
    float py = pts[p * 3 + 1];
    float pz = pts[p * 3 + 2];
    float ax = Rp[0] * px + Rp[1] * py + Rp[2] * pz;
    float ay = Rp[3] * px + Rp[4] * py + Rp[5] * pz;
    float az = Rp[6] * px + Rp[7] * py + Rp[8] * pz;
    float np2 = ax * ax + ay * ay + az * az;

    float d;
    if (sym) {
        const ull ax2 = pack2(ax, ax);
        const ull ay2 = pack2(ay, ay);
        const ull az2 = pack2(az, az);
        // 8 independent min chains (4 unrolled packed lanes x lo/hi)
        float mn0 = 3.4e38f, mn1 = 3.4e38f, mn2 = 3.4e38f, mn3 = 3.4e38f;
        float mn4 = 3.4e38f, mn5 = 3.4e38f, mn6 = 3.4e38f, mn7 = 3.4e38f;
        #pragma unroll 2
        for (int j = 0; j < NP / 2; j += 4) {
            ulonglong2 A0 = s_A[j + 0], B0 = s_B[j + 0];
            ulonglong2 A1 = s_A[j + 1], B1 = s_B[j + 1];
            ulonglong2 A2 = s_A[j + 2], B2 = s_B[j + 2];
            ulonglong2 A3 = s_A[j + 3], B3 = s_B[j + 3];

            ull d0 = fma2(ax2, A0.x, fma2(ay2, A0.y, fma2(az2, B0.x, B0.y)));
            ull d1 = fma2(ax2, A1.x, fma2(ay2, A1.y, fma2(az2, B1.x, B1.y)));
            ull d2 = fma2(ax2, A2.x, fma2(ay2, A2.y, fma2(az2, B2.x, B2.y)));
            ull d3 = fma2(ax2, A3.x, fma2(ay2, A3.y, fma2(az2, B3.x, B3.y)));

            float l0, h0, l1, h1, l2, h2, l3, h3;
            unpack2(d0, l0, h0);
            unpack2(d1, l1, h1);
            unpack2(d2, l2, h2);
            unpack2(d3, l3, h3);
            mn0 = fminf(mn0, l0);  mn1 = fminf(mn1, h0);
            mn2 = fminf(mn2, l1);  mn3 = fminf(mn3, h1);
            mn4 = fminf(mn4, l2);  mn5 = fminf(mn5, h2);
            mn6 = fminf(mn6, l3);  mn7 = fminf(mn7, h3);
        }
        float mn = fminf(fminf(fminf(mn0, mn1), fminf(mn2, mn3)),
                         fminf(fminf(mn4, mn5), fminf(mn6, mn7)));
        // max(.,0) commutes with min; add constant |xp|^2 after the min
        d = fmaxf(mn + np2, 0.f);
    } else {
        // reuse shared cache: s pair j = p/2, lo/hi by parity; xg = -0.5 * packed
        ulonglong2 A = s_A[p >> 1];
        ulonglong2 B = s_B[p >> 1];
        float gxl, gxh, gyl, gyh, gzl, gzh;
        unpack2(A.x, gxl, gxh);
        unpack2(A.y, gyl, gyh);
        unpack2(B.x, gzl, gzh);
        float gx = (p & 1) ? gxh : gxl;
        float gy = (p & 1) ? gyh : gyl;
        float gz = (p & 1) ? gzh : gzl;
        float dx = fmaf(0.5f, gx, ax);
        float dy = fmaf(0.5f, gy, ay);
        float dz = fmaf(0.5f, gz, az);
        d = dx * dx + dy * dy + dz * dz;
    }

    float contrib = valid ? 0.5f * fmaxf(d - MARGIN, 0.f) * inv_scale : 0.f;

    // ---- block reduction ----
    #pragma unroll
    for (int off = 16; off > 0; off >>= 1)
        contrib += __shfl_down_sync(0xFFFFFFFFu, contrib, off);
    if ((tid & 31) == 0) s_red[tid >> 5] = contrib;
    __syncthreads();
    if (tid < 32) {
        float v = (tid < TPB / 32) ? s_red[tid] : 0.f;
        #pragma unroll
        for (int off = 2; off > 0; off >>= 1)
            v += __shfl_down_sync(0xFFFFFFFFu, v, off);
        if (tid == 0) atomicAdd(out, v);
    }
}

extern "C" void kernel_launch(void* const* d_in, const int* in_sizes, int n_in,
                              void* d_out, int out_size) {
    const float* poses_pred   = (const float*)d_in[0];
    const float* poses_target = (const float*)d_in[1];
    const float* poses_weight = (const float*)d_in[2];
    const float* points       = (const float*)d_in[3];
    const float* symmetry     = (const float*)d_in[4];
    float* out = (float*)d_out;

    const int B = in_sizes[0] / (4 * NC);
    const float inv_scale = 1.0f / ((float)B * (float)NP);

    adl_zero_kernel<<<1, 256>>>(out, out_size);

    dim3 grid(B, CHUNKS);
    AverageDistanceLoss_kernel<<<grid, TPB>>>(
        poses_pred, poses_target, poses_weight, points, symmetry, out, inv_scale);
}

// round 5
// speedup vs baseline: 1.7059x; 1.3875x over previous
#include <cuda_runtime.h>

#define NC 22
#define NP 1024
#define BMAX 256
#define CHUNKS 8          // kernel B: blocks per symmetric batch
#define TPB_B 64          // kernel B threads (each handles 2 p's): CHUNKS*TPB_B*2 == NP
#define TPB_A 128
#define MARGIN 0.01f

typedef unsigned long long ull;

__device__ ulonglong2 g_A[BMAX][NP / 2];   // ((-2gx_e,-2gx_o),(-2gy_e,-2gy_o))
__device__ ulonglong2 g_Bt[BMAX][NP / 2];  // ((-2gz_e,-2gz_o),(|g_e|^2,|g_o|^2))
__device__ float4     g_xp[BMAX][NP];      // (ax, ay, az, |a|^2)
__device__ int        g_sym_cnt;
__device__ int        g_sym_list[BMAX];

__device__ __forceinline__ ull fma2(ull a, ull b, ull c) {
    ull d;
    asm("fma.rn.f32x2 %0, %1, %2, %3;" : "=l"(d) : "l"(a), "l"(b), "l"(c));
    return d;
}
__device__ __forceinline__ ull pack2(float lo, float hi) {
    ull d;
    asm("mov.b64 %0, {%1, %2};" : "=l"(d) : "f"(lo), "f"(hi));
    return d;
}
__device__ __forceinline__ void unpack2(ull v, float& lo, float& hi) {
    asm("mov.b64 {%0, %1}, %2;" : "=f"(lo), "=f"(hi) : "l"(v));
}

__device__ __forceinline__ void quat2rot(float w, float x, float y, float z, float* R) {
    R[0] = 1.f - 2.f * (y * y + z * z);
    R[1] = 2.f * (x * y - z * w);
    R[2] = 2.f * (x * z + y * w);
    R[3] = 2.f * (x * y + z * w);
    R[4] = 1.f - 2.f * (x * x + z * z);
    R[5] = 2.f * (y * z - x * w);
    R[6] = 2.f * (x * z - y * w);
    R[7] = 2.f * (y * z + x * w);
    R[8] = 1.f - 2.f * (x * x + y * y);
}

__global__ void adl_zero_kernel(float* out, int n) {
    int i = blockIdx.x * blockDim.x + threadIdx.x;
    if (i < n) out[i] = 0.f;
    if (i == 0) g_sym_cnt = 0;
}

// ---------------- Kernel A: prep + asymmetric diag path ----------------
__global__ __launch_bounds__(TPB_A) void adl_prep_kernel(
    const float* __restrict__ poses_pred,
    const float* __restrict__ poses_target,
    const float* __restrict__ poses_weight,
    const float* __restrict__ points,
    const float* __restrict__ symmetry,
    float* __restrict__ out,
    float inv_scale)
{
    __shared__ float s_red[TPB_A / 32];
    const int b   = blockIdx.x;
    const int tid = threadIdx.x;

    // class selection: first i with weight[b, 4i] > 0
    int  cls   = 0;
    bool valid = false;
    #pragma unroll
    for (int i = 0; i < NC; i++) {
        float w = poses_weight[b * 4 * NC + 4 * i];
        if (!valid && w > 0.f) { cls = i; valid = true; }
    }
    if (!valid) return;  // contributes 0

    const float* qp = poses_pred   + b * 4 * NC + 4 * cls;
    const float* qg = poses_target + b * 4 * NC + 4 * cls;
    float Rp[9], Rg[9];
    quat2rot(qp[0], qp[1], qp[2], qp[3], Rp);
    quat2rot(qg[0], qg[1], qg[2], qg[3], Rg);
    const bool   sym = symmetry[cls] > 0.f;
    const float* pts = points + (size_t)cls * NP * 3;

    float acc = 0.f;
    #pragma unroll
    for (int j = tid; j < NP / 2; j += TPB_A) {
        const float* p0 = pts + (size_t)(2 * j) * 3;
        float x0 = p0[0], y0 = p0[1], z0 = p0[2];
        float x1 = p0[3], y1 = p0[4], z1 = p0[5];

        float gx0 = Rg[0] * x0 + Rg[1] * y0 + Rg[2] * z0;
        float gy0 = Rg[3] * x0 + Rg[4] * y0 + Rg[5] * z0;
        float gz0 = Rg[6] * x0 + Rg[7] * y0 + Rg[8] * z0;
        float gx1 = Rg[0] * x1 + Rg[1] * y1 + Rg[2] * z1;
        float gy1 = Rg[3] * x1 + Rg[4] * y1 + Rg[5] * z1;
        float gz1 = Rg[6] * x1 + Rg[7] * y1 + Rg[8] * z1;

        float ax0 = Rp[0] * x0 + Rp[1] * y0 + Rp[2] * z0;
        float ay0 = Rp[3] * x0 + Rp[4] * y0 + Rp[5] * z0;
        float az0 = Rp[6] * x0 + Rp[7] * y0 + Rp[8] * z0;
        float ax1 = Rp[0] * x1 + Rp[1] * y1 + Rp[2] * z1;
        float ay1 = Rp[3] * x1 + Rp[4] * y1 + Rp[5] * z1;
        float az1 = Rp[6] * x1 + Rp[7] * y1 + Rp[8] * z1;

        if (sym) {
            float n0 = gx0 * gx0 + gy0 * gy0 + gz0 * gz0;
            float n1 = gx1 * gx1 + gy1 * gy1 + gz1 * gz1;
            ulonglong2 A, B;
            A.x = pack2(-2.f * gx0, -2.f * gx1);
            A.y = pack2(-2.f * gy0, -2.f * gy1);
            B.x = pack2(-2.f * gz0, -2.f * gz1);
            B.y = pack2(n0, n1);
            g_A[b][j]  = A;
            g_Bt[b][j] = B;
            g_xp[b][2 * j + 0] = make_float4(ax0, ay0, az0, ax0 * ax0 + ay0 * ay0 + az0 * az0);
            g_xp[b][2 * j + 1] = make_float4(ax1, ay1, az1, ax1 * ax1 + ay1 * ay1 + az1 * az1);
        } else {
            float dx0 = ax0 - gx0, dy0 = ay0 - gy0, dz0 = az0 - gz0;
            float dx1 = ax1 - gx1, dy1 = ay1 - gy1, dz1 = az1 - gz1;
            float d0 = dx0 * dx0 + dy0 * dy0 + dz0 * dz0;
            float d1 = dx1 * dx1 + dy1 * dy1 + dz1 * dz1;
            acc += 0.5f * fmaxf(d0 - MARGIN, 0.f) + 0.5f * fmaxf(d1 - MARGIN, 0.f);
        }
    }

    if (sym) {
        if (tid == 0) {
            int idx = atomicAdd(&g_sym_cnt, 1);
            g_sym_list[idx] = b;
        }
        return;
    }

    // block reduce asym contribution
    acc *= inv_scale;
    #pragma unroll
    for (int off = 16; off > 0; off >>= 1)
        acc += __shfl_down_sync(0xFFFFFFFFu, acc, off);
    if ((tid & 31) == 0) s_red[tid >> 5] = acc;
    __syncthreads();
    if (tid < 32) {
        float v = (tid < TPB_A / 32) ? s_red[tid] : 0.f;
        #pragma unroll
        for (int off = 2; off > 0; off >>= 1)
            v += __shfl_down_sync(0xFFFFFFFFu, v, off);
        if (tid == 0) atomicAdd(out, v);
    }
}

// ---------------- Kernel B: symmetric ADD-S, compacted & uniform ----------------
__global__ __launch_bounds__(TPB_B) void adl_sym_kernel(
    float* __restrict__ out, float inv_scale)
{
    __shared__ ulonglong2 s_A[NP / 2];
    __shared__ ulonglong2 s_B[NP / 2];
    __shared__ float s_red[TPB_B / 32];

    const int i   = blockIdx.x;
    const int cnt = g_sym_cnt;
    if (i >= cnt * CHUNKS) return;

    const int b     = g_sym_list[i / CHUNKS];
    const int chunk = i % CHUNKS;
    const int tid   = threadIdx.x;

    // stage packed target tile into shared (coalesced LDG.128 from L2)
    #pragma unroll
    for (int k = tid; k < NP / 2; k += TPB_B) {
        s_A[k] = g_A[b][k];
        s_B[k] = g_Bt[b][k];
    }
    __syncthreads();

    const int p0 = chunk * (2 * TPB_B) + tid;
    const int p1 = p0 + TPB_B;
    float4 x0 = g_xp[b][p0];
    float4 x1 = g_xp[b][p1];

    const ull ax0 = pack2(x0.x, x0.x), ay0 = pack2(x0.y, x0.y), az0 = pack2(x0.z, x0.z);
    const ull ax1 = pack2(x1.x, x1.x), ay1 = pack2(x1.y, x1.y), az1 = pack2(x1.z, x1.z);

    float m00 = 3.4e38f, m01 = 3.4e38f, m02 = 3.4e38f, m03 = 3.4e38f;
    float m10 = 3.4e38f, m11 = 3.4e38f, m12 = 3.4e38f, m13 = 3.4e38f;

    #pragma unroll 2
    for (int j = 0; j < NP / 2; j += 2) {
        ulonglong2 A0 = s_A[j + 0], B0 = s_B[j + 0];
        ulonglong2 A1 = s_A[j + 1], B1 = s_B[j + 1];

        ull c0 = fma2(az0, B0.x, B0.y);
        ull c1 = fma2(az0, B1.x, B1.y);
        ull c2 = fma2(az1, B0.x, B0.y);
        ull c3 = fma2(az1, B1.x, B1.y);
        ull t00 = fma2(ax0, A0.x, fma2(ay0, A0.y, c0));
        ull t01 = fma2(ax0, A1.x, fma2(ay0, A1.y, c1));
        ull t10 = fma2(ax1, A0.x, fma2(ay1, A0.y, c2));
        ull t11 = fma2(ax1, A1.x, fma2(ay1, A1.y, c3));

        float l, h;
        unpack2(t00, l, h);  m00 = fminf(m00, l);  m01 = fminf(m01, h);
        unpack2(t01, l, h);  m02 = fminf(m02, l);  m03 = fminf(m03, h);
        unpack2(t10, l, h);  m10 = fminf(m10, l);  m11 = fminf(m11, h);
        unpack2(t11, l, h);  m12 = fminf(m12, l);  m13 = fminf(m13, h);
    }

    float mn0 = fminf(fminf(m00, m01), fminf(m02, m03));
    float mn1 = fminf(fminf(m10, m11), fminf(m12, m13));
    // max(.,0) commutes with min; add constant |xp|^2 after the min
    float d0 = fmaxf(mn0 + x0.w, 0.f);
    float d1 = fmaxf(mn1 + x1.w, 0.f);

    float acc = (0.5f * fmaxf(d0 - MARGIN, 0.f) + 0.5f * fmaxf(d1 - MARGIN, 0.f)) * inv_scale;

    #pragma unroll
    for (int off = 16; off > 0; off >>= 1)
        acc += __shfl_down_sync(0xFFFFFFFFu, acc, off);
    if ((tid & 31) == 0) s_red[tid >> 5] = acc;
    __syncthreads();
    if (tid == 0) {
        float v = s_red[0] + s_red[1];
        atomicAdd(out, v);
    }
}

extern "C" void kernel_launch(void* const* d_in, const int* in_sizes, int n_in,
                              void* d_out, int out_size) {
    const float* poses_pred   = (const float*)d_in[0];
    const float* poses_target = (const float*)d_in[1];
    const float* poses_weight = (const float*)d_in[2];
    const float* points       = (const float*)d_in[3];
    const float* symmetry     = (const float*)d_in[4];
    float* out = (float*)d_out;

    const int B = in_sizes[0] / (4 * NC);
    const float inv_scale = 1.0f / ((float)B * (float)NP);

    adl_zero_kernel<<<1, 256>>>(out, out_size);

    adl_prep_kernel<<<B, TPB_A>>>(
        poses_pred, poses_target, poses_weight, points, symmetry, out, inv_scale);

    adl_sym_kernel<<<B * CHUNKS, TPB_B>>>(out, inv_scale);
}